// round 17
// baseline (speedup 1.0000x reference)
// R16: (a) fgemm pipeline PIPE 2->3, prefetch depth 2 (each load gets ~2 chunk
// times; removes per-chunk load-latency exposure at the barrier); (b) fuse
// recur_combine into oh_kernel. 1-pass fp16 + fused scan from R15 PASS.
#include <cuda_runtime.h>
#include <cuda_fp16.h>
#include <cstdint>
#include <math.h>

// Problem constants
#define BATCH   32
#define SEQ     1024
#define INDIM   1024
#define DDIM    1024
#define MLPDIM  2048
#define NCLS    10
#define BSROWS  (BATCH * SEQ)     // 32768
#define KCAT    (2 * INDIM)       // 2048

// GEMM tiling
#define BM 128
#define BN 128
#define BK 64
#define NKCH (KCAT / BK)          // 32 k-chunks
#define XH   (INDIM / BK)         // 16 (chunks in first half)
#define PIPE 3
#define RSTRIDE 144               // bytes per smem row (64 fp16 data + 8 pad)
#define ARR_BYTES (128 * RSTRIDE)            // 18432
#define STAGE_BYTES (2 * ARR_BYTES)          // 36864: A, B
#define SMEM_TOTAL (PIPE * STAGE_BYTES)      // 110592 -> 2 CTAs/SM
// epilogue reuse: sF[128][132] floats = 67584 B; sHA/sHB at 67584/68096

// recurrence segmentation
#define RSEG 8
#define SEGLEN (SEQ / RSEG)       // 128 == BM

// ---------------- scratch (device globals) ----------------
__device__ __align__(16) __half g_ah[(size_t)BSROWS * INDIM];   // 64 MB (A fp16)
__device__ __align__(16) __half g_bh[(size_t)DDIM * KCAT];      // [n][k] B fp16

__device__ float g_segA[RSEG * BATCH * DDIM];
__device__ float g_segB[RSEG * BATCH * DDIM];
__device__ float g_h[BATCH * DDIM];
__device__ float g_q0[BATCH * MLPDIM];
__device__ float g_q1[BATCH * MLPDIM];

__device__ __forceinline__ float sigmoidf_(float v) {
    return 1.0f / (1.0f + expf(-v));
}
__device__ __forceinline__ uint32_t smem_u32(const void* p) {
    uint32_t a;
    asm("{ .reg .u64 t; cvta.to.shared.u64 t, %1; cvt.u32.u64 %0, t; }" : "=r"(a) : "l"(p));
    return a;
}
__device__ __forceinline__ void cpasync16z(uint32_t dst, const void* gsrc, uint32_t srcbytes) {
    asm volatile("cp.async.cg.shared.global [%0], [%1], 16, %2;"
                 :: "r"(dst), "l"(__cvta_generic_to_global(gsrc)), "r"(srcbytes) : "memory");
}
__device__ __forceinline__ void cp_commit() {
    asm volatile("cp.async.commit_group;" ::: "memory");
}
template <int N>
__device__ __forceinline__ void cp_wait() {
    asm volatile("cp.async.wait_group %0;" :: "n"(N) : "memory");
}
__device__ __forceinline__ void ldsm_x4(uint32_t* r, uint32_t addr) {
    asm volatile("ldmatrix.sync.aligned.m8n8.x4.shared.b16 {%0,%1,%2,%3}, [%4];"
                 : "=r"(r[0]), "=r"(r[1]), "=r"(r[2]), "=r"(r[3]) : "r"(addr));
}
__device__ __forceinline__ void mma_f16(float* c, const uint32_t* a, const uint32_t* b) {
    asm volatile(
        "mma.sync.aligned.m16n8k16.row.col.f32.f16.f16.f32 "
        "{%0,%1,%2,%3}, {%4,%5,%6,%7}, {%8,%9}, {%0,%1,%2,%3};"
        : "+f"(c[0]), "+f"(c[1]), "+f"(c[2]), "+f"(c[3])
        : "r"(a[0]), "r"(a[1]), "r"(a[2]), "r"(a[3]), "r"(b[0]), "r"(b[1]));
}

// ---------------- convert x -> fp16 [r][0:1024] ----------------
__global__ __launch_bounds__(256) void convert_x_kernel(const float* __restrict__ x)
{
    size_t idx = (size_t)blockIdx.x * blockDim.x + threadIdx.x;  // BSROWS*128
    size_t r = idx >> 7;
    int j = (int)(idx & 127) * 8;

    const float4* src = reinterpret_cast<const float4*>(x + r * INDIM + j);
    float4 v0 = src[0], v1 = src[1];
    float vs[8] = {v0.x, v0.y, v0.z, v0.w, v1.x, v1.y, v1.z, v1.w};

    uint32_t hw[4];
    #pragma unroll
    for (int i = 0; i < 4; i++) {
        __half h0 = __float2half_rn(vs[2*i]);
        __half h1 = __float2half_rn(vs[2*i+1]);
        hw[i] = (uint32_t)__half_as_ushort(h0) | ((uint32_t)__half_as_ushort(h1) << 16);
    }
    reinterpret_cast<uint4*>(g_ah)[(r * INDIM + j) >> 3] = make_uint4(hw[0], hw[1], hw[2], hw[3]);
}

// ---------------- convert weights: Bcat^T [n][k] fp16 ----------------
__global__ __launch_bounds__(256) void convert_w_kernel(
    const float* __restrict__ Ww, const float* __restrict__ Vw)
{
    __shared__ float s[32][33];
    int kt = blockIdx.x;     // 0..63
    int nt = blockIdx.y;     // 0..31
    int k0 = kt * 32, n0 = nt * 32;
    int tid = threadIdx.x;

    const float* src = (k0 < INDIM) ? (Ww + (size_t)k0 * (3 * DDIM))
                                    : (Vw + (size_t)(k0 - INDIM) * (3 * DDIM));
    #pragma unroll
    for (int i = 0; i < 4; i++) {
        int lin = tid + i * 256;
        int kk = lin >> 5, nn = lin & 31;
        s[kk][nn] = src[(size_t)kk * (3 * DDIM) + n0 + nn];
    }
    __syncthreads();

    #pragma unroll
    for (int i = 0; i < 2; i++) {
        int lin = tid + i * 256;
        int nn = lin >> 4;
        int kp = lin & 15;
        float a = s[kp * 2][nn], b = s[kp * 2 + 1][nn];
        __half h0 = __float2half_rn(a);
        __half h1 = __float2half_rn(b);
        size_t off = ((size_t)(n0 + nn) * KCAT + k0 + kp * 2) >> 1;
        reinterpret_cast<uint32_t*>(g_bh)[off] =
            (uint32_t)__half_as_ushort(h0) | ((uint32_t)__half_as_ushort(h1) << 16);
    }
}

// ---------------- main GEMM + fused segment scan ----------------
// grid (8 n, 256 m), 256 threads = 8 warps (4 m x 2 n), warp tile 32x64.
// 2 CTAs/SM; 3-stage pipe, depth-2 prefetch; one __syncthreads per k-chunk.
__global__ __launch_bounds__(256, 2) void fgemm_mma_kernel(const float* __restrict__ Vb)
{
    extern __shared__ __align__(16) char smem[];
    const uint32_t sbase = smem_u32(smem);
    const int tid = threadIdx.x;
    const int wid = tid >> 5, lane = tid & 31;
    const int mwarp = wid >> 1, nwarp = wid & 1;
    const int g = lane >> 2, t4 = lane & 3;

    const size_t r0 = (size_t)blockIdx.y * BM;
    const int n0 = blockIdx.x * BN;

    // ldmatrix per-lane byte offsets (144B row stride; conflict-free)
    const uint32_t a_off = (((lane >> 3) & 1) * 8 + (lane & 7)) * RSTRIDE + (lane >> 4) * 16;
    const uint32_t b_off = (((lane >> 4) & 1) * 8 + (lane & 7)) * RSTRIDE + ((lane >> 3) & 1) * 16;

    float c[2][8][4];
    #pragma unroll
    for (int mt = 0; mt < 2; mt++)
        #pragma unroll
        for (int nt = 0; nt < 8; nt++)
            #pragma unroll
            for (int i = 0; i < 4; i++) c[mt][nt][i] = 0.0f;

    // prefetch: 2048 16B chunks per stage (A 128x8, B 128x8), 256 threads -> 8 each
    auto prefetch = [&](int kc, int s) {
        const uint32_t st = sbase + (uint32_t)s * STAGE_BYTES;
        #pragma unroll
        for (int i = 0; i < 8; i++) {
            int cidx = tid + i * 256;
            if (cidx < 1024) {
                // A: 128 rows x 8 chunks
                int row = cidx >> 3;
                int ch  = cidx & 7;
                uint32_t dst = st + row * RSTRIDE + ch * 16;
                const void* src;
                uint32_t sz = 16;
                if (kc < XH) {
                    src = g_ah + (r0 + row) * INDIM + kc * BK + ch * 8;
                } else {
                    bool z = (row == 0) && ((r0 & (SEQ - 1)) == 0);
                    src = z ? (const void*)g_ah
                            : (const void*)(g_ah + (r0 + row - 1) * INDIM + (kc - XH) * BK + ch * 8);
                    sz = z ? 0u : 16u;
                }
                cpasync16z(dst, src, sz);
            } else {
                // B: 128 rows x 8 chunks
                int cidx2 = cidx - 1024;
                int row  = cidx2 >> 3;
                int ch   = cidx2 & 7;
                uint32_t dst = st + ARR_BYTES + row * RSTRIDE + ch * 16;
                cpasync16z(dst, g_bh + (size_t)(n0 + row) * KCAT + kc * BK + ch * 8, 16);
            }
        }
        cp_commit();
    };

    prefetch(0, 0);
    prefetch(1, 1);

    for (int kc = 0; kc < NKCH; kc++) {
        int s = kc % PIPE;
        cp_wait<1>();        // chunk kc's group complete; kc+1's may remain
        __syncthreads();
        // stage (kc+2)%PIPE == stage of chunk kc-1: all warps finished reading
        // it during iteration kc-1; the barrier above proves it.
        if (kc + 2 < NKCH) prefetch(kc + 2, (kc + 2) % PIPE);
        else cp_commit();    // keep group accounting uniform

        const uint32_t sA = sbase + (uint32_t)s * STAGE_BYTES;
        const uint32_t sB = sA + ARR_BYTES;

        #pragma unroll
        for (int h = 0; h < 4; h++) {          // four k16 steps (BK=64)
            uint32_t aH[2][4];
            #pragma unroll
            for (int mt = 0; mt < 2; mt++) {
                uint32_t rb = (uint32_t)(mwarp * 32 + mt * 16) * RSTRIDE + h * 32;
                ldsm_x4(aH[mt], sA + rb + a_off);
            }
            #pragma unroll
            for (int p = 0; p < 4; p++) {
                uint32_t bh[4];
                uint32_t nb = (uint32_t)(nwarp * 64 + p * 16) * RSTRIDE + h * 32;
                ldsm_x4(bh, sB + nb + b_off);
                mma_f16(c[0][2*p],   aH[0], bh);
                mma_f16(c[0][2*p+1], aH[0], bh + 2);
                mma_f16(c[1][2*p],   aH[1], bh);
                mma_f16(c[1][2*p+1], aH[1], bh + 2);
            }
        }
    }

    // ---- fused epilogue: f -> smem, segment affine scan -> g_segA/B ----
    cp_wait<0>();
    __syncthreads();   // all warps done reading stages; smem is reusable

    float* sF = reinterpret_cast<float*>(smem);                    // [128][132]
    float* sHA = reinterpret_cast<float*>(smem + 67584);           // [128]
    float* sHB = reinterpret_cast<float*>(smem + 68096);           // [128]

    #pragma unroll
    for (int mt = 0; mt < 2; mt++) {
        #pragma unroll
        for (int nt = 0; nt < 8; nt++) {
            int m = mwarp * 32 + mt * 16 + g;       // 0..127 (t within segment)
            int col = nwarp * 64 + nt * 8 + t4 * 2; // 0..127
            float b0 = Vb[n0 + col], b1 = Vb[n0 + col + 1];
            sF[m * 132 + col]           = sigmoidf_(c[mt][nt][0] + b0);
            sF[m * 132 + col + 1]       = sigmoidf_(c[mt][nt][1] + b1);
            sF[(m + 8) * 132 + col]     = sigmoidf_(c[mt][nt][2] + b0);
            sF[(m + 8) * 132 + col + 1] = sigmoidf_(c[mt][nt][3] + b1);
        }
    }
    __syncthreads();

    // scan: c_t = f_t * (c_{t-1} + 1). Each column's 128-chain split in two
    // 64-halves (tid>>7 selects half), composed via smem.
    {
        int col = tid & 127;
        int half = tid >> 7;
        float A = 1.0f, B = 0.0f;
        const float* p = sF + (half * 64) * 132 + col;
        #pragma unroll 8
        for (int t = 0; t < 64; t++) {
            float f = p[t * 132];
            A *= f;
            B = f * (B + 1.0f);
        }
        if (half == 0) { sHA[col] = A; sHB[col] = B; }
        __syncthreads();
        if (half == 1) {
            float A0 = sHA[col], B0 = sHB[col];
            float Af = A0 * A;          // composite over 128 steps
            float Bf = A * B0 + B;
            int b   = (int)(r0 >> 10);          // batch
            int seg = (int)((r0 >> 7) & 7);     // segment within sequence
            size_t out = (size_t)seg * (BATCH * DDIM) + (size_t)b * DDIM + n0 + col;
            g_segA[out] = Af;
            g_segB[out] = Bf;
        }
    }
}

// ---------------- combine segments + o at last timestep -> h ----------------
__global__ __launch_bounds__(256) void coh_kernel(
    const float* __restrict__ x,
    const float* __restrict__ Ww,
    const float* __restrict__ Vw,
    const float* __restrict__ Vb)
{
    int idx = blockIdx.x * blockDim.x + threadIdx.x;   // 0..32767
    int b = idx >> 10;
    int d = idx & 1023;

    // combine segment affine maps -> c_last
    float cval = 0.0f;
    #pragma unroll
    for (int s = 0; s < RSEG; s++)
        cval = g_segA[s * (BATCH * DDIM) + idx] * cval + g_segB[s * (BATCH * DDIM) + idx];

    // o_pre at last timestep
    const float* xlast = x + ((size_t)b * SEQ + (SEQ - 1)) * INDIM;
    const float* xprev = xlast - INDIM;
    const float* wcol  = Ww + 2 * DDIM + d;
    const float* vcol  = Vw + 2 * DDIM + d;
    float acc = Vb[2 * DDIM + d];
    #pragma unroll 4
    for (int k = 0; k < INDIM; k++) {
        acc += xlast[k] * wcol[(size_t)k * (3 * DDIM)];
        acc += xprev[k] * vcol[(size_t)k * (3 * DDIM)];
    }
    g_h[idx] = cval * sigmoidf_(acc);
}

// ---------------- MLP layers (M=32, N=2048) ----------------
__global__ __launch_bounds__(256) void mlp_kernel(
    const float* __restrict__ W,
    const float* __restrict__ bias,
    int KDIM, int layer)
{
    const float* Ain = (layer == 0) ? g_h  : g_q0;
    float*       out = (layer == 0) ? g_q0 : g_q1;

    __shared__ float As[32][33];
    __shared__ float Bs[32][33];

    int n0   = blockIdx.x * 32;
    int tid  = threadIdx.x;
    int tcol = tid & 31;
    int trow = tid >> 5;

    float acc[4] = {0.f, 0.f, 0.f, 0.f};

    for (int k0 = 0; k0 < KDIM; k0 += 32) {
        #pragma unroll
        for (int i = 0; i < 4; i++) {
            int lin = tid + i * 256;
            int m = lin >> 5, kk = lin & 31;
            As[m][kk] = Ain[(size_t)m * KDIM + k0 + kk];
            Bs[m][kk] = W[(size_t)(k0 + m) * MLPDIM + n0 + kk];
        }
        __syncthreads();
        #pragma unroll
        for (int kk = 0; kk < 32; kk++) {
            float bv = Bs[kk][tcol];
            #pragma unroll
            for (int i = 0; i < 4; i++)
                acc[i] += As[trow * 4 + i][kk] * bv;
        }
        __syncthreads();
    }
    #pragma unroll
    for (int i = 0; i < 4; i++) {
        float v = acc[i] + bias[n0 + tcol];
        out[(size_t)(trow * 4 + i) * MLPDIM + n0 + tcol] = fmaxf(v, 0.0f);
    }
}

// ---------------- head ----------------
__global__ __launch_bounds__(256) void head_kernel(
    const float* __restrict__ W2,
    const float* __restrict__ b2,
    float* __restrict__ out)
{
    int warp = (blockIdx.x * blockDim.x + threadIdx.x) >> 5;
    int lane = threadIdx.x & 31;
    if (warp >= BATCH * NCLS) return;
    int m = warp / NCLS;
    int n = warp % NCLS;
    const float* a = g_q1 + (size_t)m * MLPDIM;
    float s = 0.0f;
    for (int k = lane; k < MLPDIM; k += 32)
        s += a[k] * W2[(size_t)k * NCLS + n];
    #pragma unroll
    for (int off = 16; off; off >>= 1)
        s += __shfl_xor_sync(0xffffffffu, s, off);
    if (lane == 0) out[warp] = s + b2[n];
}

// ============================================================================
extern "C" void kernel_launch(void* const* d_in, const int* in_sizes, int n_in,
                              void* d_out, int out_size)
{
    const float* x   = (const float*)d_in[0];
    const float* Ww  = (const float*)d_in[1];
    const float* Vw  = (const float*)d_in[2];
    const float* Vb  = (const float*)d_in[3];
    const float* l0w = (const float*)d_in[4];
    const float* l0b = (const float*)d_in[5];
    const float* l1w = (const float*)d_in[6];
    const float* l1b = (const float*)d_in[7];
    const float* l2w = (const float*)d_in[8];
    const float* l2b = (const float*)d_in[9];
    float* out = (float*)d_out;

    cudaFuncSetAttribute(fgemm_mma_kernel,
                         cudaFuncAttributeMaxDynamicSharedMemorySize, SMEM_TOTAL);

    // 0. convert to fp16 scratch
    convert_x_kernel<<<(BSROWS * 128) / 256, 256>>>(x);
    convert_w_kernel<<<dim3(KCAT / 32, DDIM / 32), 256>>>(Ww, Vw);

    // 1. f-gate GEMM + fused segment scan -> g_segA/g_segB
    fgemm_mma_kernel<<<dim3(DDIM / BN, BSROWS / BM), 256, SMEM_TOTAL>>>(Vb);

    // 2. combine segments + o gate -> h
    coh_kernel<<<(BATCH * DDIM) / 256, 256>>>(x, Ww, Vw, Vb);

    // 3. MLP
    mlp_kernel<<<MLPDIM / 32, 256>>>(l0w, l0b, DDIM,   0);
    mlp_kernel<<<MLPDIM / 32, 256>>>(l1w, l1b, MLPDIM, 1);

    // 4. head
    head_kernel<<<(BATCH * NCLS * 32 + 255) / 256, 256>>>(l2w, l2b, out);
}